// round 11
// baseline (speedup 1.0000x reference)
#include <cuda_runtime.h>
#include <cuda_bf16.h>

#define NB 16
#define HH 512
#define WW 512
#define PLANE (HH * WW)
#define TOTAL (NB * PLANE)

// Padded layout: 516 rows x 520 cols. Data at rows 1..512, cols 4..515.
// Guard cells are zero from module load and NEVER written -> stay zero forever.
// Gather coords clamped to [-1,512]; clamped/out-of-range corners read zero
// guard cells or carry zero weight == zeros-padding grid_sample semantics.
#define SP 520
#define SROWS 516
#define PP (SROWS * SP)
#define POFF(y, x) (((y) + 1) * SP + ((x) + 4))

__device__ float2 g_dispA[NB * PP];
__device__ float2 g_dispB[NB * PP];
__device__ float  g_ldA[NB * PP];
__device__ float  g_ldB[NB * PP];

// Lerp-form bilinear: no explicit corner weights.
__device__ __forceinline__ float2 bilin2(const float2* __restrict__ plane, float sy, float sx) {
    sy = fminf(fmaxf(sy, -1.f), 512.f);
    sx = fminf(fmaxf(sx, -1.f), 512.f);
    float fy0 = floorf(sy), fx0 = floorf(sx);
    float wy = sy - fy0, wx = sx - fx0;
    int y0 = (int)fy0, x0 = (int)fx0;
    int base = POFF(y0, x0);
    float2 v00 = plane[base];
    float2 v01 = plane[base + 1];
    float2 v10 = plane[base + SP];
    float2 v11 = plane[base + SP + 1];
    float tx_ = v00.x + wx * (v01.x - v00.x);
    float ty_ = v00.y + wx * (v01.y - v00.y);
    float bx_ = v10.x + wx * (v11.x - v10.x);
    float by_ = v10.y + wx * (v11.y - v10.y);
    return make_float2(tx_ + wy * (bx_ - tx_), ty_ + wy * (by_ - ty_));
}

__device__ __forceinline__ float bilin1(const float* __restrict__ plane, float sy, float sx) {
    sy = fminf(fmaxf(sy, -1.f), 512.f);
    sx = fminf(fmaxf(sx, -1.f), 512.f);
    float fy0 = floorf(sy), fx0 = floorf(sx);
    float wy = sy - fy0, wx = sx - fx0;
    int y0 = (int)fy0, x0 = (int)fx0;
    int base = POFF(y0, x0);
    float v00 = plane[base];
    float v01 = plane[base + 1];
    float v10 = plane[base + SP];
    float v11 = plane[base + SP + 1];
    float t_ = v00 + wx * (v01 - v00);
    float b_ = v10 + wx * (v11 - v10);
    return t_ + wy * (b_ - t_);
}

// logdet(I + eps*J) 4-term trace series via power-sum recurrence.
__device__ __forceinline__ float logdet_series(float J00, float J01, float J10, float J11) {
    const float eps = 0.0078125f;  // 2^-7
    float t = J00 + J11;
    float d = J00 * J11 - J01 * J10;
    float s2 = t * t - 2.f * d;
    float s3 = t * s2 - d * t;
    float s4 = t * s3 - d * s2;
    const float e2 = eps * eps, e3 = e2 * eps, e4 = e3 * eps;
    return eps * t - 0.5f * e2 * s2 + (e3 * (1.f / 3.f)) * s3 - 0.25f * e4 * s4;
}

// Init (4 pixels/thread): disp0 = eps*vel, ldjac0 from Sobel Jacobian.
__global__ void __launch_bounds__(256) init_kernel(const float* __restrict__ vel) {
    int tid = blockIdx.x * blockDim.x + threadIdx.x;
    if (tid >= TOTAL / 4) return;
    int idx = tid << 2;
    int n = idx >> 18;            // / PLANE
    int rem = idx & (PLANE - 1);
    int y = rem >> 9;
    int x = rem & (WW - 1);       // multiple of 4

    const float* v0 = vel + (size_t)(2 * n) * PLANE;
    const float* v1 = v0 + PLANE;

    const float eps = 0.0078125f;

    int ym = max(y - 1, 0), yp = min(y + 1, HH - 1);
    int rmo = ym * WW, rco = y * WW, rpo = yp * WW;
    int xl = max(x - 1, 0), xr = min(x + 4, WW - 1);

    // 6-col windows: w[0]=x-1 .. w[5]=x+4 (clamped at edges)
    float am[6], ac[6], ap[6], bm[6], bc[6], bp[6];
    {
        float4 t;
        am[0] = v0[rmo + xl]; t = *(const float4*)(v0 + rmo + x); am[1]=t.x; am[2]=t.y; am[3]=t.z; am[4]=t.w; am[5] = v0[rmo + xr];
        ac[0] = v0[rco + xl]; t = *(const float4*)(v0 + rco + x); ac[1]=t.x; ac[2]=t.y; ac[3]=t.z; ac[4]=t.w; ac[5] = v0[rco + xr];
        ap[0] = v0[rpo + xl]; t = *(const float4*)(v0 + rpo + x); ap[1]=t.x; ap[2]=t.y; ap[3]=t.z; ap[4]=t.w; ap[5] = v0[rpo + xr];
        bm[0] = v1[rmo + xl]; t = *(const float4*)(v1 + rmo + x); bm[1]=t.x; bm[2]=t.y; bm[3]=t.z; bm[4]=t.w; bm[5] = v1[rmo + xr];
        bc[0] = v1[rco + xl]; t = *(const float4*)(v1 + rco + x); bc[1]=t.x; bc[2]=t.y; bc[3]=t.z; bc[4]=t.w; bc[5] = v1[rco + xr];
        bp[0] = v1[rpo + xl]; t = *(const float4*)(v1 + rpo + x); bp[1]=t.x; bp[2]=t.y; bp[3]=t.z; bp[4]=t.w; bp[5] = v1[rpo + xr];
    }

    int po = n * PP + POFF(y, x);
    *(float4*)(g_dispA + po)     = make_float4(eps * ac[1], eps * bc[1], eps * ac[2], eps * bc[2]);
    *(float4*)(g_dispA + po + 2) = make_float4(eps * ac[3], eps * bc[3], eps * ac[4], eps * bc[4]);

    float ld[4];
#pragma unroll
    for (int j = 0; j < 4; j++) {
        float J00 = 0.125f * ((ap[j] + 2.f * ap[j+1] + ap[j+2]) - (am[j] + 2.f * am[j+1] + am[j+2]));
        float J01 = 0.125f * ((am[j+2] + 2.f * ac[j+2] + ap[j+2]) - (am[j] + 2.f * ac[j] + ap[j]));
        float J10 = 0.125f * ((bp[j] + 2.f * bp[j+1] + bp[j+2]) - (bm[j] + 2.f * bm[j+1] + bm[j+2]));
        float J11 = 0.125f * ((bm[j+2] + 2.f * bc[j+2] + bp[j+2]) - (bm[j] + 2.f * bc[j] + bp[j]));
        ld[j] = logdet_series(J00, J01, J10, J11);
    }
    *(float4*)(g_ldA + po) = make_float4(ld[0], ld[1], ld[2], ld[3]);
}

// One squaring step, fused, 4 VERTICALLY adjacent pixels/thread (1 col x 4 rows).
// Warp = 32 contiguous columns x 4 rows: per-instruction gather footprint stays
// ~32px wide (2-3 lines), while each thread carries 4 independent gather chains
// -> ~2x MLP at equal wavefront cost.
template <bool SRC_A, bool FINAL>
__global__ void __launch_bounds__(256) step_kernel(float* __restrict__ out_disp,
                                                   float* __restrict__ out_ld) {
    int bx = blockIdx.x;
    int n  = bx >> 8;            // 256 tiles per image (16 col-tiles * 16 row-tiles)
    int t  = bx & 255;
    int tx = t & 15;             // col tile (32 cols)
    int ty = t >> 4;             // row tile (32 rows)
    int lane = threadIdx.x & 31;
    int w    = threadIdx.x >> 5; // 0..7 row group within tile
    int x = (tx << 5) + lane;
    int y = (ty << 5) + (w << 2);   // rows y..y+3

    const float2* __restrict__ dp = (SRC_A ? g_dispA : g_dispB) + (size_t)n * PP;
    const float*  __restrict__ lp = (SRC_A ? g_ldA   : g_ldB)   + (size_t)n * PP;

    const float SC = (float)HH / (float)(HH - 1);

    int po = POFF(y, x);
    float2 d[4];
    float  lc[4];
#pragma unroll
    for (int j = 0; j < 4; j++) {
        d[j]  = dp[po + j * SP];
        lc[j] = lp[po + j * SP];
    }

    float fx = (float)x;
    float dn_x[4], dn_y[4];
#pragma unroll
    for (int j = 0; j < 4; j++) {
        float fy = (float)(y + j);
        float2 s = bilin2(dp, (fy + d[j].x) * SC - 0.5f, (fx + d[j].y) * SC - 0.5f);
        dn_x[j] = d[j].x + s.x;
        dn_y[j] = d[j].y + s.y;
    }

    float l[4];
#pragma unroll
    for (int j = 0; j < 4; j++) {
        float fy = (float)(y + j);
        l[j] = lc[j] + bilin1(lp, (fy + dn_x[j]) * SC - 0.5f, (fx + dn_y[j]) * SC - 0.5f);
    }

    if (FINAL) {
        float* od0 = out_disp + (size_t)(2 * n) * PLANE;      // channel 0 plane
        float* od1 = out_disp + (size_t)(2 * n + 1) * PLANE;  // channel 1 plane
        float* ol  = out_ld   + (size_t)n * PLANE;
#pragma unroll
        for (int j = 0; j < 4; j++) {
            int rem = ((y + j) << 9) + x;
            od0[rem] = dn_x[j];
            od1[rem] = dn_y[j];
            ol[rem]  = l[j];
        }
    } else {
        float2* __restrict__ ddst = (SRC_A ? g_dispB : g_dispA) + (size_t)n * PP;
        float*  __restrict__ ldst = (SRC_A ? g_ldB   : g_ldA)   + (size_t)n * PP;
#pragma unroll
        for (int j = 0; j < 4; j++) {
            ddst[po + j * SP] = make_float2(dn_x[j], dn_y[j]);
            ldst[po + j * SP] = l[j];
        }
    }
}

extern "C" void kernel_launch(void* const* d_in, const int* in_sizes, int n_in,
                              void* d_out, int out_size) {
    const float* vel = (const float*)d_in[0];
    float* out = (float*)d_out;
    float* out_disp = out;
    float* out_ld = out + (size_t)NB * 2 * PLANE;

    const int threads = 256;
    const int init_blocks = (TOTAL / 4 + threads - 1) / threads;
    const int step_blocks = NB * 256;   // 16 col-tiles * 16 row-tiles per image

    init_kernel<<<init_blocks, threads>>>(vel);
    // 7 steps: A->B, B->A, A->B, B->A, A->B, B->A, A->out
    step_kernel<true,  false><<<step_blocks, threads>>>(out_disp, out_ld);
    step_kernel<false, false><<<step_blocks, threads>>>(out_disp, out_ld);
    step_kernel<true,  false><<<step_blocks, threads>>>(out_disp, out_ld);
    step_kernel<false, false><<<step_blocks, threads>>>(out_disp, out_ld);
    step_kernel<true,  false><<<step_blocks, threads>>>(out_disp, out_ld);
    step_kernel<false, false><<<step_blocks, threads>>>(out_disp, out_ld);
    step_kernel<true,  true ><<<step_blocks, threads>>>(out_disp, out_ld);
}